// round 7
// baseline (speedup 1.0000x reference)
#include <cuda_runtime.h>
#include <cstdint>

// Bayer mosaic channel select:
//   out[b,i,j] = img[b, c, i, j]
//   c = 1 if (i+j) even; else 2 if i even; else 0
// Row-parity view:
//   i even: j even -> ch1, j odd -> ch2
//   i odd : j even -> ch0, j odd -> ch1
//
// One CTA per ROW PAIR (i even, i+1 odd): 1024 threads, each thread one
// float4. Per-CTA memory extents:
//   read  ch1 rows [i, i+1]  -> 16 KB contiguous (both parities use ch1)
//   read  ch2 row i          ->  8 KB contiguous
//   read  ch0 row i+1        ->  8 KB contiguous
//   write out rows [i, i+1]  -> 16 KB contiguous
// Maximal DRAM open-row / L2-slice run length. Per-thread shape identical to
// the best kernels: 2x LDG.128 + 1x STG.128, shift/add indexing only.

static constexpr int C = 3;
static constexpr int H = 2048;
static constexpr int W = 2048;
static constexpr int W4 = W / 4;   // 512 float4 per row

__global__ __launch_bounds__(1024)
void bayer_kernel(const float* __restrict__ img, float* __restrict__ out) {
    const int t   = threadIdx.x;            // [0,1024)
    const int sub = t >> 9;                 // 0: even row of pair, 1: odd row
    const int j4  = t & (W4 - 1);           // float4 index within row
    const int i   = (blockIdx.x << 1) | sub;  // actual row
    const int b   = blockIdx.y;

    // Channels for this row: cA serves even j, cB serves odd j
    // sub==0 (i even): cA=1, cB=2 ; sub==1 (i odd): cA=0, cB=1
    const int cA = 1 - sub;
    const int cB = 2 - sub;

    const int64_t plane = (int64_t)H * W;
    const int64_t row_base = (int64_t)b * C * plane + (int64_t)i * W + (int64_t)j4 * 4;

    const float4 a  = *reinterpret_cast<const float4*>(img + row_base + (int64_t)cA * plane);
    const float4 bv = *reinterpret_cast<const float4*>(img + row_base + (int64_t)cB * plane);

    float4 o;
    o.x = a.x;   // even j
    o.y = bv.y;  // odd j
    o.z = a.z;   // even j
    o.w = bv.w;  // odd j

    const int64_t out_idx = ((int64_t)b * H + i) * W + (int64_t)j4 * 4;
    *reinterpret_cast<float4*>(out + out_idx) = o;
}

extern "C" void kernel_launch(void* const* d_in, const int* in_sizes, int n_in,
                              void* d_out, int out_size) {
    const float* img = (const float*)d_in[0];
    float* out = (float*)d_out;

    dim3 grid(H / 2, 8);    // (1024 row-pairs, 8 batches) = 8192 CTAs
    bayer_kernel<<<grid, 1024>>>(img, out);
}

// round 8
// speedup vs baseline: 1.0104x; 1.0104x over previous
#include <cuda_runtime.h>
#include <cstdint>

// Bayer mosaic channel select:
//   out[b,i,j] = img[b, c, i, j]
//   c = 1 if (i+j) even; else 2 if i even; else 0
// Row-parity view:
//   i even: j even -> ch1, j odd -> ch2
//   i odd : j even -> ch0, j odd -> ch1
//
// Best empirical variant (R6): one CTA per image row, 512 threads, each
// thread one float4. Per CTA: two contiguous 8KB read extents + one 8KB
// write extent. Per-thread shape: 2x LDG.128 + 1x STG.128.
// This round: pure 32-bit index arithmetic (all byte offsets < 4GB;
// img = 384MB, out = 128MB), shift/add only.

static constexpr unsigned H = 2048;
static constexpr unsigned W = 2048;
static constexpr unsigned PLANE = H * W;         // 4,194,304 elements

__global__ __launch_bounds__(512)
void bayer_kernel(const float* __restrict__ img, float* __restrict__ out) {
    const unsigned j  = threadIdx.x << 2;        // element index within row
    const unsigned i  = blockIdx.x;              // row
    const unsigned b  = blockIdx.y;              // batch
    const unsigned sub = i & 1u;                 // 0: even row, 1: odd row

    // Channels for this row: cA serves even j, cB serves odd j
    const unsigned cA = 1u - sub;                // even row -> 1, odd row -> 0
    const unsigned cB = 2u - sub;                // even row -> 2, odd row -> 1

    // 32-bit element offsets (max b*3*PLANE + ... < 101M elements, fits)
    const unsigned row_base = (b * 3u + cA) * PLANE + i * W + j;   // cA plane
    const unsigned delta    = (cB - cA) * PLANE;                   // = PLANE

    const float4 a  = *reinterpret_cast<const float4*>(img + row_base);
    const float4 bv = *reinterpret_cast<const float4*>(img + row_base + delta);

    float4 o;
    o.x = a.x;   // even j
    o.y = bv.y;  // odd j
    o.z = a.z;   // even j
    o.w = bv.w;  // odd j

    const unsigned out_idx = (b * H + i) * W + j;
    *reinterpret_cast<float4*>(out + out_idx) = o;
}

extern "C" void kernel_launch(void* const* d_in, const int* in_sizes, int n_in,
                              void* d_out, int out_size) {
    const float* img = (const float*)d_in[0];
    float* out = (float*)d_out;

    dim3 grid(H, 8);     // (2048 rows, 8 batches) = 16384 CTAs of 512 threads
    bayer_kernel<<<grid, 512>>>(img, out);
}

// round 9
// speedup vs baseline: 1.0109x; 1.0005x over previous
#include <cuda_runtime.h>
#include <cstdint>

// Bayer mosaic channel select:
//   out[b,i,j] = img[b, c, i, j]
//   c = 1 if (i+j) even; else 2 if i even; else 0
// Row-parity view:
//   i even: j even -> ch1, j odd -> ch2
//   i odd : j even -> ch0, j odd -> ch1
//
// FINAL (converged, hardware-floor-bound): traffic floor is 384 MB
// (256 MB read with inherent 2:1 sector amplification + 128 MB write);
// at the LTS chip cap (~6300 B/cyc) that is ~55.6 us, which the best ncu
// measurements sit on. Best empirical configuration across 8 rounds:
//   - one CTA per image row, 512 threads, one float4 per thread
//   - per CTA: two contiguous 8 KB read extents + one 8 KB write extent
//   - per thread: 2x plain LDG.128 + 1x plain STG.128 (cache hints, MLP
//     batching, persistence, and row-pairing all measured as regressions)
//   - pure 32-bit shift/add indexing (all offsets < 4 GB), 16 regs

static constexpr unsigned H = 2048;
static constexpr unsigned W = 2048;
static constexpr unsigned PLANE = H * W;         // 4,194,304 elements

__global__ __launch_bounds__(512)
void bayer_kernel(const float* __restrict__ img, float* __restrict__ out) {
    const unsigned j  = threadIdx.x << 2;        // element index within row
    const unsigned i  = blockIdx.x;              // row
    const unsigned b  = blockIdx.y;              // batch
    const unsigned sub = i & 1u;                 // 0: even row, 1: odd row

    // Channels for this row: cA serves even j, cB serves odd j
    const unsigned cA = 1u - sub;                // even row -> 1, odd row -> 0

    const unsigned row_base = (b * 3u + cA) * PLANE + i * W + j;   // cA plane
    // cB = cA + 1 always (even: 1->2, odd: 0->1), so delta = PLANE

    const float4 a  = *reinterpret_cast<const float4*>(img + row_base);
    const float4 bv = *reinterpret_cast<const float4*>(img + row_base + PLANE);

    float4 o;
    o.x = a.x;   // even j
    o.y = bv.y;  // odd j
    o.z = a.z;   // even j
    o.w = bv.w;  // odd j

    const unsigned out_idx = (b * H + i) * W + j;
    *reinterpret_cast<float4*>(out + out_idx) = o;
}

extern "C" void kernel_launch(void* const* d_in, const int* in_sizes, int n_in,
                              void* d_out, int out_size) {
    const float* img = (const float*)d_in[0];
    float* out = (float*)d_out;

    dim3 grid(H, 8);     // (2048 rows, 8 batches) = 16384 CTAs of 512 threads
    bayer_kernel<<<grid, 512>>>(img, out);
}